// round 1
// baseline (speedup 1.0000x reference)
#include <cuda_runtime.h>
#include <cstdint>

#define BB 64
#define TT 2048
#define JJ 256
#define DD 200
#define DP 202          // padded row stride in floats (odd in 8B units -> conflict-free 64b LDS)
#define TROWS 32        // t-rows per CTA
#define JC 64           // u chunk rows in smem
#define NTHREADS 256

typedef unsigned long long ull;

union f2u { ull u; float2 f; };

__device__ __forceinline__ void ffma2(ull& d, ull a, ull b) {
    asm("fma.rn.f32x2 %0, %1, %2, %0;" : "+l"(d) : "l"(a), "l"(b));
}
__device__ __forceinline__ ull bcast2(float a) {
    ull r;
    asm("mov.b64 %0, {%1, %1};" : "=l"(r) : "r"(__float_as_uint(a)));
    return r;
}

// scratch (device globals: no allocation allowed)
__device__ float g_alpha_u[BB * JJ];
__device__ float g_m[BB * TT];
__device__ float g_q2c[BB * DD];

// ---------------------------------------------------------------------------
// alpha_u[b,j] = dot(u[b,j,:], w_u)
// ---------------------------------------------------------------------------
__global__ void alpha_u_kernel(const float* __restrict__ u, const float* __restrict__ w_u) {
    int row  = blockIdx.x * 8 + (threadIdx.x >> 5);
    int lane = threadIdx.x & 31;
    const float* ur = u + (size_t)row * DD;
    float s = 0.f;
    for (int c = lane; c < DD; c += 32) s += ur[c] * w_u[c];
    #pragma unroll
    for (int o = 16; o > 0; o >>= 1) s += __shfl_xor_sync(0xffffffffu, s, o);
    if (lane == 0) g_alpha_u[row] = s;
}

// ---------------------------------------------------------------------------
// Main fused kernel: per CTA = (b, 32 t-rows)
//   s[r][j] = alpha_h[r] + alpha_u[j] + sum_d (h*w_hu)[r][d]*u[j][d] + bias
//   a = softmax_j(s); m[b,t] = max_j s; c2q = a @ u
//   writes g[...,0:D]=h, g[...,D:2D]=c2q, g[...,2D:3D]=h*c2q
// ---------------------------------------------------------------------------
extern __shared__ float smem[];

__device__ __forceinline__ void stage_u_chunk(float* u_s, const float* u, int bb, int jc, int tid) {
    const float2* usrc = reinterpret_cast<const float2*>(u + ((size_t)bb * JJ + (size_t)jc * JC) * DD);
    #pragma unroll 5
    for (int i = tid; i < JC * 100; i += NTHREADS) {
        int r = i / 100, c = i % 100;
        *reinterpret_cast<float2*>(&u_s[r * DP + 2 * c]) = usrc[i];
    }
}

__global__ __launch_bounds__(NTHREADS, 2)
void bidaf_main_kernel(const float* __restrict__ h, const float* __restrict__ u,
                       const float* __restrict__ w_h, const float* __restrict__ w_hu,
                       const float* __restrict__ b_h, const float* __restrict__ b_u,
                       const float* __restrict__ b_hu, float* __restrict__ g) {
    float* hw_s  = smem;                           // TROWS*DP
    float* u_s   = smem + TROWS * DP;              // JC*DP
    float* c2q_s = u_s;                            // overlay (used after PV done)
    float* s_s   = smem + TROWS * DP + JC * DP;    // TROWS*JJ
    float* al_s  = s_s + TROWS * JJ;               // TROWS
    float* inv_s = al_s + TROWS;                   // TROWS

    const int tid  = threadIdx.x;
    const int lane = tid & 31;
    const int wid  = tid >> 5;
    const int bb   = blockIdx.y;
    const int t0   = blockIdx.x * TROWS;

    const float2* hsrc = reinterpret_cast<const float2*>(h + ((size_t)bb * TT + t0) * DD);

    // ---- stage hw = h * w_hu ----
    #pragma unroll 4
    for (int i = tid; i < TROWS * 100; i += NTHREADS) {
        int r = i / 100, c = i % 100;
        float2 hv = hsrc[i];
        float2 wv = *reinterpret_cast<const float2*>(w_hu + 2 * c);
        float2 o; o.x = hv.x * wv.x; o.y = hv.y * wv.y;
        *reinterpret_cast<float2*>(&hw_s[r * DP + 2 * c]) = o;
    }

    // ---- alpha_h per row (deterministic warp reduction; h is L1-hot) ----
    #pragma unroll
    for (int k = 0; k < 4; ++k) {
        int r = wid * 4 + k;
        const float* hr = h + ((size_t)bb * TT + t0 + r) * DD;
        float s = 0.f;
        for (int c = lane; c < DD; c += 32) s += hr[c] * w_h[c];
        #pragma unroll
        for (int o = 16; o > 0; o >>= 1) s += __shfl_xor_sync(0xffffffffu, s, o);
        if (lane == 0) al_s[r] = s;
    }

    // ---- QK: s_raw[r][j] = sum_d hw[r][d]*u[j][d] ----
    // thread tile: 4 rows x 8 j (j = jt + 32k). jt in 0..31, rt in 0..7.
    const int a_ = tid & 15, bq = (tid >> 4) & 7, cc = tid >> 7;
    const int jt = a_ + 16 * cc;
    const int rt = bq;

    ull acc[4][8];
    #pragma unroll
    for (int i = 0; i < 4; ++i)
        #pragma unroll
        for (int k = 0; k < 8; ++k) acc[i][k] = 0ull;

    #pragma unroll
    for (int jc = 0; jc < 4; ++jc) {
        __syncthreads();
        stage_u_chunk(u_s, u, bb, jc, tid);
        __syncthreads();
        #pragma unroll 4
        for (int dp = 0; dp < 100; ++dp) {
            ull u20 = *reinterpret_cast<const ull*>(&u_s[jt * DP + 2 * dp]);
            ull u21 = *reinterpret_cast<const ull*>(&u_s[(jt + 32) * DP + 2 * dp]);
            #pragma unroll
            for (int i = 0; i < 4; ++i) {
                ull hw2 = *reinterpret_cast<const ull*>(&hw_s[(rt * 4 + i) * DP + 2 * dp]);
                ffma2(acc[i][2 * jc],     hw2, u20);
                ffma2(acc[i][2 * jc + 1], hw2, u21);
            }
        }
    }

    // ---- combine + write s ----
    const float bias = __ldg(b_h) + __ldg(b_u) + __ldg(b_hu);
    float au[8];
    #pragma unroll
    for (int k = 0; k < 8; ++k) au[k] = g_alpha_u[bb * JJ + jt + 32 * k];
    #pragma unroll
    for (int i = 0; i < 4; ++i) {
        int r = rt * 4 + i;
        float ah = al_s[r];
        #pragma unroll
        for (int k = 0; k < 8; ++k) {
            f2u v; v.u = acc[i][k];
            s_s[r * JJ + jt + 32 * k] = v.f.x + v.f.y + ah + au[k] + bias;
        }
    }
    __syncthreads();

    // ---- softmax per row (exact, J=256 in smem); also m[b,t] = rowmax ----
    #pragma unroll
    for (int k = 0; k < 4; ++k) {
        int r = wid * 4 + k;
        float vals[8];
        float mx = -3.4e38f;
        #pragma unroll
        for (int m = 0; m < 8; ++m) {
            vals[m] = s_s[r * JJ + lane + 32 * m];
            mx = fmaxf(mx, vals[m]);
        }
        #pragma unroll
        for (int o = 16; o > 0; o >>= 1) mx = fmaxf(mx, __shfl_xor_sync(0xffffffffu, mx, o));
        float sum = 0.f;
        #pragma unroll
        for (int m = 0; m < 8; ++m) {
            float e = __expf(vals[m] - mx);
            s_s[r * JJ + lane + 32 * m] = e;   // store unnormalized exp
            sum += e;
        }
        #pragma unroll
        for (int o = 16; o > 0; o >>= 1) sum += __shfl_xor_sync(0xffffffffu, sum, o);
        if (lane == 0) {
            g_m[bb * TT + t0 + r] = mx;
            inv_s[r] = 1.0f / sum;
        }
    }

    // ---- PV: c2q[r][d] = inv_s[r] * sum_j a[r][j]*u[j][d] ----
    // thread: 2 rows (rg), d-pairs dp = dg + 8k, j-subset j % 2 == jg; reduce over jg via shfl xor 8
    const int rg = tid >> 4;          // 0..15 -> rows 2rg, 2rg+1
    const int dg = tid & 7;
    const int jg = (tid >> 3) & 1;
    const int r0 = 2 * rg, r1 = r0 + 1;

    ull pacc0[13], pacc1[13];
    #pragma unroll
    for (int k = 0; k < 13; ++k) { pacc0[k] = 0ull; pacc1[k] = 0ull; }

    #pragma unroll 1
    for (int jc = 0; jc < 4; ++jc) {
        __syncthreads();
        stage_u_chunk(u_s, u, bb, jc, tid);
        __syncthreads();
        #pragma unroll 2
        for (int jjl = 0; jjl < JC; jjl += 2) {
            int jl = jjl + jg;
            int j  = jc * JC + jl;
            ull a02 = bcast2(s_s[r0 * JJ + j]);
            ull a12 = bcast2(s_s[r1 * JJ + j]);
            #pragma unroll
            for (int k = 0; k < 13; ++k) {
                int dp = dg + 8 * k;
                if (dp < 100) {
                    ull u2 = *reinterpret_cast<const ull*>(&u_s[jl * DP + 2 * dp]);
                    ffma2(pacc0[k], a02, u2);
                    ffma2(pacc1[k], a12, u2);
                }
            }
        }
    }
    __syncthreads();   // all PV reads of u_s done before overlaying c2q_s

    // reduce over jg (lane xor 8; partner has same rg/dg) and write c2q
    {
        float iv0 = inv_s[r0], iv1 = inv_s[r1];
        #pragma unroll
        for (int k = 0; k < 13; ++k) {
            int dp = dg + 8 * k;
            f2u v0; v0.u = pacc0[k];
            f2u v1; v1.u = pacc1[k];
            v0.f.x += __shfl_xor_sync(0xffffffffu, v0.f.x, 8);
            v0.f.y += __shfl_xor_sync(0xffffffffu, v0.f.y, 8);
            v1.f.x += __shfl_xor_sync(0xffffffffu, v1.f.x, 8);
            v1.f.y += __shfl_xor_sync(0xffffffffu, v1.f.y, 8);
            if (jg == 0 && dp < 100) {
                float2 o0; o0.x = v0.f.x * iv0; o0.y = v0.f.y * iv0;
                float2 o1; o1.x = v1.f.x * iv1; o1.y = v1.f.y * iv1;
                *reinterpret_cast<float2*>(&c2q_s[r0 * DP + 2 * dp]) = o0;
                *reinterpret_cast<float2*>(&c2q_s[r1 * DP + 2 * dp]) = o1;
            }
        }
    }
    __syncthreads();

    // ---- epilogue: g[:,0:D]=h, g[:,D:2D]=c2q, g[:,2D:3D]=h*c2q ----
    float2* gbase = reinterpret_cast<float2*>(g + ((size_t)bb * TT + t0) * (4 * DD));
    #pragma unroll 4
    for (int i = tid; i < TROWS * 100; i += NTHREADS) {
        int r = i / 100, c = i % 100;
        float2 hv = hsrc[i];
        float2 cq = *reinterpret_cast<const float2*>(&c2q_s[r * DP + 2 * c]);
        size_t ro = (size_t)r * 400;   // 800 floats = 400 float2 per row
        gbase[ro + c] = hv;
        gbase[ro + 100 + c] = cq;
        float2 p; p.x = hv.x * cq.x; p.y = hv.y * cq.y;
        gbase[ro + 200 + c] = p;
    }
}

// ---------------------------------------------------------------------------
// q2c[b,:] = sum_t softmax_t(m[b,:])[t] * h[b,t,:]   (one CTA per b)
// ---------------------------------------------------------------------------
__global__ __launch_bounds__(NTHREADS)
void q2c_kernel(const float* __restrict__ h) {
    __shared__ float beta[TT];
    __shared__ float red[8];
    const int b = blockIdx.x, tid = threadIdx.x;
    const int lane = tid & 31, wid = tid >> 5;

    float lm = -3.4e38f;
    for (int i = tid; i < TT; i += NTHREADS) {
        float v = g_m[b * TT + i];
        beta[i] = v;
        lm = fmaxf(lm, v);
    }
    #pragma unroll
    for (int o = 16; o > 0; o >>= 1) lm = fmaxf(lm, __shfl_xor_sync(0xffffffffu, lm, o));
    if (lane == 0) red[wid] = lm;
    __syncthreads();
    float bm = red[0];
    #pragma unroll
    for (int i = 1; i < 8; ++i) bm = fmaxf(bm, red[i]);
    __syncthreads();

    float ls = 0.f;
    for (int i = tid; i < TT; i += NTHREADS) {
        float e = __expf(beta[i] - bm);
        beta[i] = e;
        ls += e;
    }
    #pragma unroll
    for (int o = 16; o > 0; o >>= 1) ls += __shfl_xor_sync(0xffffffffu, ls, o);
    if (lane == 0) red[wid] = ls;
    __syncthreads();
    float bs = 0.f;
    #pragma unroll
    for (int i = 0; i < 8; ++i) bs += red[i];
    const float inv = 1.0f / bs;

    if (tid < DD) {
        const float* hb = h + (size_t)b * TT * DD + tid;
        float a0 = 0.f, a1 = 0.f, a2 = 0.f, a3 = 0.f;
        #pragma unroll 4
        for (int t = 0; t < TT; t += 4) {
            a0 += beta[t]     * hb[(size_t)t * DD];
            a1 += beta[t + 1] * hb[(size_t)(t + 1) * DD];
            a2 += beta[t + 2] * hb[(size_t)(t + 2) * DD];
            a3 += beta[t + 3] * hb[(size_t)(t + 3) * DD];
        }
        g_q2c[b * DD + tid] = (a0 + a1 + a2 + a3) * inv;
    }
}

// ---------------------------------------------------------------------------
// g[:,3D:4D] = h * q2c (broadcast over t)
// ---------------------------------------------------------------------------
__global__ void g3_kernel(const float* __restrict__ h, float* __restrict__ g) {
    int idx = blockIdx.x * NTHREADS + threadIdx.x;   // over B*T*100 float2
    int tl  = idx / 100;          // b*T + t
    int c   = idx % 100;
    int b   = tl >> 11;           // / 2048
    float2 hv = reinterpret_cast<const float2*>(h)[idx];
    float2 q  = *reinterpret_cast<const float2*>(&g_q2c[b * DD + 2 * c]);
    float2 p; p.x = hv.x * q.x; p.y = hv.y * q.y;
    reinterpret_cast<float2*>(g)[(size_t)tl * 400 + 300 + c] = p;
}

// ---------------------------------------------------------------------------
extern "C" void kernel_launch(void* const* d_in, const int* in_sizes, int n_in,
                              void* d_out, int out_size) {
    const float* h    = (const float*)d_in[0];
    const float* u    = (const float*)d_in[1];
    const float* w_h  = (const float*)d_in[2];
    const float* b_h  = (const float*)d_in[3];
    const float* w_u  = (const float*)d_in[4];
    const float* b_u  = (const float*)d_in[5];
    const float* w_hu = (const float*)d_in[6];
    const float* b_hu = (const float*)d_in[7];
    float* g = (float*)d_out;

    const int smem_bytes = (TROWS * DP + JC * DP + TROWS * JJ + 2 * TROWS) * 4; // 110592
    // Idempotent; first (non-captured) correctness call sets it before graph capture.
    cudaFuncSetAttribute(bidaf_main_kernel, cudaFuncAttributeMaxDynamicSharedMemorySize, smem_bytes);

    alpha_u_kernel<<<(BB * JJ) / 8, NTHREADS>>>(u, w_u);

    dim3 gridC(TT / TROWS, BB);
    bidaf_main_kernel<<<gridC, NTHREADS, smem_bytes>>>(h, u, w_h, w_hu, b_h, b_u, b_hu, g);

    q2c_kernel<<<BB, NTHREADS>>>(h);

    g3_kernel<<<(BB * TT * 100) / NTHREADS, NTHREADS>>>(h, g);
}

// round 2
// speedup vs baseline: 1.1821x; 1.1821x over previous
#include <cuda_runtime.h>
#include <cstdint>

#define BB 64
#define TT 2048
#define JJ 256
#define DD 200
#define DP 202          // padded smem row stride (conflict-free 64b column access)
#define TROWS 32
#define JC 64
#define NTHREADS 256

typedef unsigned long long ull;
union f2u { ull u; float2 f; };

__device__ __forceinline__ void ffma2(ull& d, ull a, ull b) {
    asm("fma.rn.f32x2 %0, %1, %2, %0;" : "+l"(d) : "l"(a), "l"(b));
}
__device__ __forceinline__ ull bcast2(float a) {
    ull r;
    asm("mov.b64 %0, {%1, %1};" : "=l"(r) : "r"(__float_as_uint(a)));
    return r;
}

// scratch (device globals: no allocation allowed)
__device__ float g_alpha_u[BB * JJ];
__device__ float g_m[BB * TT];
__device__ float g_q2c[BB * DD];
__device__ float g_part[BB * 8 * DD];

// ---------------------------------------------------------------------------
// alpha_u[b,j] = dot(u[b,j,:], w_u)
// ---------------------------------------------------------------------------
__global__ void alpha_u_kernel(const float* __restrict__ u, const float* __restrict__ w_u) {
    int row  = blockIdx.x * 8 + (threadIdx.x >> 5);
    int lane = threadIdx.x & 31;
    const float* ur = u + (size_t)row * DD;
    float s = 0.f;
    for (int c = lane; c < DD; c += 32) s += ur[c] * w_u[c];
    #pragma unroll
    for (int o = 16; o > 0; o >>= 1) s += __shfl_xor_sync(0xffffffffu, s, o);
    if (lane == 0) g_alpha_u[row] = s;
}

// ---------------------------------------------------------------------------
extern __shared__ float smem[];

__device__ __forceinline__ void stage_u_chunk(float* u_s, const float* u, int bb, int jc, int tid) {
    const float2* usrc = reinterpret_cast<const float2*>(u + ((size_t)bb * JJ + (size_t)jc * JC) * DD);
    #pragma unroll 5
    for (int i = tid; i < JC * 100; i += NTHREADS) {
        int r = i / 100, c = i % 100;
        *reinterpret_cast<float2*>(&u_s[r * DP + 2 * c]) = usrc[i];
    }
}

__global__ __launch_bounds__(NTHREADS, 2)
void bidaf_main_kernel(const float* __restrict__ h, const float* __restrict__ u,
                       const float* __restrict__ w_h, const float* __restrict__ w_hu,
                       const float* __restrict__ b_h, const float* __restrict__ b_u,
                       const float* __restrict__ b_hu, float* __restrict__ g) {
    float* hw_s  = smem;                           // TROWS*DP
    float* u_s   = smem + TROWS * DP;              // JC*DP
    float* c2q_s = u_s;                            // overlay (after PV done)
    float* s_s   = smem + TROWS * DP + JC * DP;    // TROWS*JJ
    float* al_s  = s_s + TROWS * JJ;               // TROWS
    float* inv_s = al_s + TROWS;                   // TROWS

    const int tid  = threadIdx.x;
    const int lane = tid & 31;
    const int wid  = tid >> 5;
    const int bb   = blockIdx.y;
    const int t0   = blockIdx.x * TROWS;

    const float2* hsrc = reinterpret_cast<const float2*>(h + ((size_t)bb * TT + t0) * DD);

    // ---- stage hw = h * w_hu ----
    #pragma unroll 4
    for (int i = tid; i < TROWS * 100; i += NTHREADS) {
        int r = i / 100, c = i % 100;
        float2 hv = hsrc[i];
        float2 wv = *reinterpret_cast<const float2*>(w_hu + 2 * c);
        float2 o; o.x = hv.x * wv.x; o.y = hv.y * wv.y;
        *reinterpret_cast<float2*>(&hw_s[r * DP + 2 * c]) = o;
    }

    // ---- alpha_h per row ----
    #pragma unroll
    for (int k = 0; k < 4; ++k) {
        int r = wid * 4 + k;
        const float* hr = h + ((size_t)bb * TT + t0 + r) * DD;
        float s = 0.f;
        for (int c = lane; c < DD; c += 32) s += hr[c] * w_h[c];
        #pragma unroll
        for (int o = 16; o > 0; o >>= 1) s += __shfl_xor_sync(0xffffffffu, s, o);
        if (lane == 0) al_s[r] = s;
    }

    // ---- QK: s_raw[r][j] = sum_d hw[r][d]*u[j][d] ----
    // thread tile: 4 rows x 4 j, 2-way dp-split (tid>>7).
    // jt in 0..15, rt in 0..7, ds in {0,1}.
    const int jt = tid & 15;
    const int rt = (tid >> 4) & 7;
    const int ds = tid >> 7;
    const int dp0 = ds * 50;

    #pragma unroll 1
    for (int jc = 0; jc < 4; ++jc) {
        __syncthreads();                 // prior users of u_s / s_s done
        stage_u_chunk(u_s, u, bb, jc, tid);

        ull acc[4][4];
        #pragma unroll
        for (int i = 0; i < 4; ++i)
            #pragma unroll
            for (int k = 0; k < 4; ++k) acc[i][k] = 0ull;

        __syncthreads();                 // u chunk ready

        #pragma unroll 2
        for (int dpi = 0; dpi < 50; ++dpi) {
            const int dp = dp0 + dpi;
            ull uu[4];
            #pragma unroll
            for (int k = 0; k < 4; ++k)
                uu[k] = *reinterpret_cast<const ull*>(&u_s[(jt + 16 * k) * DP + 2 * dp]);
            #pragma unroll
            for (int i = 0; i < 4; ++i) {
                ull hw2 = *reinterpret_cast<const ull*>(&hw_s[(rt * 4 + i) * DP + 2 * dp]);
                #pragma unroll
                for (int k = 0; k < 4; ++k) ffma2(acc[i][k], hw2, uu[k]);
            }
        }

        // combine the two dp halves through smem
        if (ds == 0) {
            #pragma unroll
            for (int i = 0; i < 4; ++i)
                #pragma unroll
                for (int k = 0; k < 4; ++k) {
                    f2u v; v.u = acc[i][k];
                    s_s[(rt * 4 + i) * JJ + jc * JC + jt + 16 * k] = v.f.x + v.f.y;
                }
        }
        __syncthreads();
        if (ds == 1) {
            #pragma unroll
            for (int i = 0; i < 4; ++i)
                #pragma unroll
                for (int k = 0; k < 4; ++k) {
                    f2u v; v.u = acc[i][k];
                    s_s[(rt * 4 + i) * JJ + jc * JC + jt + 16 * k] += v.f.x + v.f.y;
                }
        }
    }
    __syncthreads();

    // ---- softmax per row (adds alpha terms + bias here) ----
    const float bias = __ldg(b_h) + __ldg(b_u) + __ldg(b_hu);
    #pragma unroll
    for (int k = 0; k < 4; ++k) {
        int r = wid * 4 + k;
        float ah = al_s[r] + bias;
        float vals[8];
        float mx = -3.4e38f;
        #pragma unroll
        for (int m = 0; m < 8; ++m) {
            vals[m] = s_s[r * JJ + lane + 32 * m] + ah + g_alpha_u[bb * JJ + lane + 32 * m];
            mx = fmaxf(mx, vals[m]);
        }
        #pragma unroll
        for (int o = 16; o > 0; o >>= 1) mx = fmaxf(mx, __shfl_xor_sync(0xffffffffu, mx, o));
        float sum = 0.f;
        #pragma unroll
        for (int m = 0; m < 8; ++m) {
            float e = __expf(vals[m] - mx);
            s_s[r * JJ + lane + 32 * m] = e;   // store unnormalized exp
            sum += e;
        }
        #pragma unroll
        for (int o = 16; o > 0; o >>= 1) sum += __shfl_xor_sync(0xffffffffu, sum, o);
        if (lane == 0) {
            g_m[bb * TT + t0 + r] = mx;
            inv_s[r] = 1.0f / sum;
        }
    }

    // ---- PV: c2q[r][d] = inv[r] * sum_j a[r][j]*u[j][d] ----
    const int rg = tid >> 4;          // rows 2rg, 2rg+1
    const int dg = tid & 7;
    const int jg = (tid >> 3) & 1;
    const int r0 = 2 * rg, r1 = r0 + 1;

    ull pacc0[13], pacc1[13];
    #pragma unroll
    for (int k = 0; k < 13; ++k) { pacc0[k] = 0ull; pacc1[k] = 0ull; }

    #pragma unroll 1
    for (int jc = 0; jc < 4; ++jc) {
        __syncthreads();
        stage_u_chunk(u_s, u, bb, jc, tid);
        __syncthreads();
        #pragma unroll 2
        for (int jjl = 0; jjl < JC; jjl += 2) {
            int jl = jjl + jg;
            int j  = jc * JC + jl;
            ull a02 = bcast2(s_s[r0 * JJ + j]);
            ull a12 = bcast2(s_s[r1 * JJ + j]);
            #pragma unroll
            for (int k = 0; k < 13; ++k) {
                int dp = dg + 8 * k;
                if (dp < 100) {
                    ull u2 = *reinterpret_cast<const ull*>(&u_s[jl * DP + 2 * dp]);
                    ffma2(pacc0[k], a02, u2);
                    ffma2(pacc1[k], a12, u2);
                }
            }
        }
    }
    __syncthreads();   // all PV reads of u_s done before overlaying c2q_s

    // reduce over jg (shfl xor 8) and write c2q
    {
        float iv0 = inv_s[r0], iv1 = inv_s[r1];
        #pragma unroll
        for (int k = 0; k < 13; ++k) {
            int dp = dg + 8 * k;
            f2u v0; v0.u = pacc0[k];
            f2u v1; v1.u = pacc1[k];
            v0.f.x += __shfl_xor_sync(0xffffffffu, v0.f.x, 8);
            v0.f.y += __shfl_xor_sync(0xffffffffu, v0.f.y, 8);
            v1.f.x += __shfl_xor_sync(0xffffffffu, v1.f.x, 8);
            v1.f.y += __shfl_xor_sync(0xffffffffu, v1.f.y, 8);
            if (jg == 0 && dp < 100) {
                float2 o0; o0.x = v0.f.x * iv0; o0.y = v0.f.y * iv0;
                float2 o1; o1.x = v1.f.x * iv1; o1.y = v1.f.y * iv1;
                *reinterpret_cast<float2*>(&c2q_s[r0 * DP + 2 * dp]) = o0;
                *reinterpret_cast<float2*>(&c2q_s[r1 * DP + 2 * dp]) = o1;
            }
        }
    }
    __syncthreads();

    // ---- epilogue: g[:,0:D]=h, g[:,D:2D]=c2q, g[:,2D:3D]=h*c2q (float4) ----
    const float4* hsrc4 = reinterpret_cast<const float4*>(h + ((size_t)bb * TT + t0) * DD);
    float4* gbase = reinterpret_cast<float4*>(g + ((size_t)bb * TT + t0) * (4 * DD));
    #pragma unroll 4
    for (int i = tid; i < TROWS * 50; i += NTHREADS) {
        int r = i / 50, c = i % 50;
        float4 hv = hsrc4[i];
        float2 cqa = *reinterpret_cast<const float2*>(&c2q_s[r * DP + 4 * c]);
        float2 cqb = *reinterpret_cast<const float2*>(&c2q_s[r * DP + 4 * c + 2]);
        float4 cq; cq.x = cqa.x; cq.y = cqa.y; cq.z = cqb.x; cq.w = cqb.y;
        size_t ro = (size_t)r * 200;   // 800 floats = 200 float4 per row
        gbase[ro + c] = hv;
        gbase[ro + 50 + c] = cq;
        float4 p; p.x = hv.x * cq.x; p.y = hv.y * cq.y; p.z = hv.z * cq.z; p.w = hv.w * cq.w;
        gbase[ro + 100 + c] = p;
    }
}

// ---------------------------------------------------------------------------
// beta[b,:] = softmax_t(m[b,:]) written in place into g_m
// ---------------------------------------------------------------------------
__global__ __launch_bounds__(NTHREADS)
void beta_kernel() {
    __shared__ float red[8];
    const int b = blockIdx.x, tid = threadIdx.x;
    const int lane = tid & 31, wid = tid >> 5;

    float lm = -3.4e38f;
    float vals[8];
    #pragma unroll
    for (int k = 0; k < 8; ++k) {
        vals[k] = g_m[b * TT + tid + k * NTHREADS];
        lm = fmaxf(lm, vals[k]);
    }
    #pragma unroll
    for (int o = 16; o > 0; o >>= 1) lm = fmaxf(lm, __shfl_xor_sync(0xffffffffu, lm, o));
    if (lane == 0) red[wid] = lm;
    __syncthreads();
    float bm = red[0];
    #pragma unroll
    for (int i = 1; i < 8; ++i) bm = fmaxf(bm, red[i]);
    __syncthreads();

    float ls = 0.f;
    #pragma unroll
    for (int k = 0; k < 8; ++k) {
        vals[k] = __expf(vals[k] - bm);
        ls += vals[k];
    }
    #pragma unroll
    for (int o = 16; o > 0; o >>= 1) ls += __shfl_xor_sync(0xffffffffu, ls, o);
    if (lane == 0) red[wid] = ls;
    __syncthreads();
    float bs = 0.f;
    #pragma unroll
    for (int i = 0; i < 8; ++i) bs += red[i];
    const float inv = 1.0f / bs;
    #pragma unroll
    for (int k = 0; k < 8; ++k)
        g_m[b * TT + tid + k * NTHREADS] = vals[k] * inv;
}

// ---------------------------------------------------------------------------
// q2c partial: CTA (p,b) sums t in [p*256, p*256+256)
// ---------------------------------------------------------------------------
__global__ __launch_bounds__(NTHREADS)
void q2c_part_kernel(const float* __restrict__ h) {
    const int p = blockIdx.x, b = blockIdx.y, tid = threadIdx.x;
    if (tid < DD) {
        const float* hb = h + ((size_t)b * TT + p * 256) * DD + tid;
        const float* bt = &g_m[b * TT + p * 256];
        float a0 = 0.f, a1 = 0.f, a2 = 0.f, a3 = 0.f;
        #pragma unroll 4
        for (int t = 0; t < 256; t += 4) {
            a0 += bt[t]     * hb[(size_t)t * DD];
            a1 += bt[t + 1] * hb[(size_t)(t + 1) * DD];
            a2 += bt[t + 2] * hb[(size_t)(t + 2) * DD];
            a3 += bt[t + 3] * hb[(size_t)(t + 3) * DD];
        }
        g_part[(b * 8 + p) * DD + tid] = a0 + a1 + a2 + a3;
    }
}

__global__ void q2c_reduce_kernel() {
    int idx = blockIdx.x * NTHREADS + threadIdx.x;
    if (idx < BB * DD) {
        int b = idx / DD, d = idx % DD;
        float s = 0.f;
        #pragma unroll
        for (int p = 0; p < 8; ++p) s += g_part[(b * 8 + p) * DD + d];
        g_q2c[idx] = s;
    }
}

// ---------------------------------------------------------------------------
// g[:,3D:4D] = h * q2c (broadcast over t), float4
// ---------------------------------------------------------------------------
__global__ void g3_kernel(const float* __restrict__ h, float* __restrict__ g) {
    int idx = blockIdx.x * NTHREADS + threadIdx.x;   // over B*T*50 float4
    int tl  = idx / 50;           // b*T + t
    int c   = idx % 50;
    int b   = tl >> 11;           // / 2048
    float4 hv = reinterpret_cast<const float4*>(h)[idx];
    float4 q  = *reinterpret_cast<const float4*>(&g_q2c[b * DD + 4 * c]);
    float4 p; p.x = hv.x * q.x; p.y = hv.y * q.y; p.z = hv.z * q.z; p.w = hv.w * q.w;
    reinterpret_cast<float4*>(g)[(size_t)tl * 200 + 150 + c] = p;
}

// ---------------------------------------------------------------------------
extern "C" void kernel_launch(void* const* d_in, const int* in_sizes, int n_in,
                              void* d_out, int out_size) {
    const float* h    = (const float*)d_in[0];
    const float* u    = (const float*)d_in[1];
    const float* w_h  = (const float*)d_in[2];
    const float* b_h  = (const float*)d_in[3];
    const float* w_u  = (const float*)d_in[4];
    const float* b_u  = (const float*)d_in[5];
    const float* w_hu = (const float*)d_in[6];
    const float* b_hu = (const float*)d_in[7];
    float* g = (float*)d_out;

    const int smem_bytes = (TROWS * DP + JC * DP + TROWS * JJ + 2 * TROWS) * 4; // 110592
    cudaFuncSetAttribute(bidaf_main_kernel, cudaFuncAttributeMaxDynamicSharedMemorySize, smem_bytes);

    alpha_u_kernel<<<(BB * JJ) / 8, NTHREADS>>>(u, w_u);

    dim3 gridC(TT / TROWS, BB);
    bidaf_main_kernel<<<gridC, NTHREADS, smem_bytes>>>(h, u, w_h, w_hu, b_h, b_u, b_hu, g);

    beta_kernel<<<BB, NTHREADS>>>();

    dim3 gridP(8, BB);
    q2c_part_kernel<<<gridP, NTHREADS>>>(h);
    q2c_reduce_kernel<<<(BB * DD + NTHREADS - 1) / NTHREADS, NTHREADS>>>();

    g3_kernel<<<(BB * TT * 50) / NTHREADS, NTHREADS>>>(h, g);
}

// round 3
// speedup vs baseline: 1.6250x; 1.3746x over previous
#include <cuda_runtime.h>
#include <cstdint>

#define BB 64
#define TT 2048
#define JJ 256
#define DD 200
#define DP 204          // padded smem row stride in floats (16B-aligned rows)
#define TROWS 32
#define JC 64
#define NTHREADS 256

typedef unsigned long long ull;
union f2u { ull u; float2 f; };
union f4u { float4 v; ull u[2]; };

__device__ __forceinline__ void ffma2(ull& d, ull a, ull b) {
    asm("fma.rn.f32x2 %0, %1, %2, %0;" : "+l"(d) : "l"(a), "l"(b));
}
__device__ __forceinline__ ull bcast2(float a) {
    ull r;
    asm("mov.b64 %0, {%1, %1};" : "=l"(r) : "r"(__float_as_uint(a)));
    return r;
}

// scratch (device globals: no allocation allowed)
__device__ float g_alpha_u[BB * JJ];
__device__ float g_m[BB * TT];
__device__ float g_q2c[BB * DD];
__device__ float g_part[BB * 8 * DD];

// ---------------------------------------------------------------------------
// g[:, 0:D] = h  (independent of everything; launched first)
// ---------------------------------------------------------------------------
__global__ void copy_h_kernel(const float* __restrict__ h, float* __restrict__ g) {
    int idx = blockIdx.x * NTHREADS + threadIdx.x;   // over B*T*50 float4
    int tl  = idx / 50;
    int c   = idx % 50;
    float4 hv = reinterpret_cast<const float4*>(h)[idx];
    reinterpret_cast<float4*>(g)[(size_t)tl * 200 + c] = hv;
}

// ---------------------------------------------------------------------------
// alpha_u[b,j] = dot(u[b,j,:], w_u)   (quarter launches for ncu positioning)
// ---------------------------------------------------------------------------
__global__ void alpha_u_kernel(const float* __restrict__ u, const float* __restrict__ w_u,
                               int row_off) {
    int row  = row_off + blockIdx.x * 8 + (threadIdx.x >> 5);
    int lane = threadIdx.x & 31;
    const float* ur = u + (size_t)row * DD;
    float s = 0.f;
    for (int c = lane; c < DD; c += 32) s += ur[c] * w_u[c];
    #pragma unroll
    for (int o = 16; o > 0; o >>= 1) s += __shfl_xor_sync(0xffffffffu, s, o);
    if (lane == 0) g_alpha_u[row] = s;
}

// ---------------------------------------------------------------------------
extern __shared__ float smem[];

__device__ __forceinline__ void stage_u_async(float* u_s, const float* u, int bb, int jc, int tid) {
    const float4* usrc = reinterpret_cast<const float4*>(u + ((size_t)bb * JJ + (size_t)jc * JC) * DD);
    uint32_t base = (uint32_t)__cvta_generic_to_shared(u_s);
    #pragma unroll
    for (int k = 0; k < 13; ++k) {
        int i = tid + k * NTHREADS;
        if (i < JC * 50) {
            int r = i / 50, c = i % 50;
            uint32_t dst = base + (uint32_t)(r * DP + 4 * c) * 4u;
            asm volatile("cp.async.cg.shared.global [%0], [%1], 16;" :: "r"(dst), "l"(usrc + i));
        }
    }
    asm volatile("cp.async.commit_group;");
}
__device__ __forceinline__ void stage_wait() {
    asm volatile("cp.async.wait_group 0;");
}

__global__ __launch_bounds__(NTHREADS, 2)
void bidaf_main_kernel(const float* __restrict__ h, const float* __restrict__ u,
                       const float* __restrict__ w_h, const float* __restrict__ w_hu,
                       const float* __restrict__ b_h, const float* __restrict__ b_u,
                       const float* __restrict__ b_hu, float* __restrict__ g) {
    float* hw_s  = smem;                           // TROWS*DP
    float* u_s   = smem + TROWS * DP;              // JC*DP
    float* c2q_s = u_s;                            // overlay (after PV done)
    float* s_s   = smem + TROWS * DP + JC * DP;    // TROWS*JJ
    float* al_s  = s_s + TROWS * JJ;               // TROWS
    float* inv_s = al_s + TROWS;                   // TROWS

    const int tid  = threadIdx.x;
    const int lane = tid & 31;
    const int wid  = tid >> 5;
    const int bb   = blockIdx.y;
    const int t0   = blockIdx.x * TROWS;

    const float4* hsrc4 = reinterpret_cast<const float4*>(h + ((size_t)bb * TT + t0) * DD);

    // ---- stage hw = h * w_hu (float4) ----
    #pragma unroll 4
    for (int i = tid; i < TROWS * 50; i += NTHREADS) {
        int r = i / 50, c = i % 50;
        float4 hv = hsrc4[i];
        float4 wv = *reinterpret_cast<const float4*>(w_hu + 4 * c);
        float4 o; o.x = hv.x * wv.x; o.y = hv.y * wv.y; o.z = hv.z * wv.z; o.w = hv.w * wv.w;
        *reinterpret_cast<float4*>(&hw_s[r * DP + 4 * c]) = o;
    }

    // ---- alpha_h per row ----
    #pragma unroll
    for (int k = 0; k < 4; ++k) {
        int r = wid * 4 + k;
        const float* hr = h + ((size_t)bb * TT + t0 + r) * DD;
        float s = 0.f;
        for (int c = lane; c < DD; c += 32) s += hr[c] * w_h[c];
        #pragma unroll
        for (int o = 16; o > 0; o >>= 1) s += __shfl_xor_sync(0xffffffffu, s, o);
        if (lane == 0) al_s[r] = s;
    }

    // ---- QK: s_raw[r][j] = sum_d hw[r][d]*u[j][d] ----
    // thread tile: 4 rows x 4 j, 2-way d-split (ds). q indexes float4 groups (4 floats).
    const int jt = tid & 15;
    const int rt = (tid >> 4) & 7;
    const int ds = tid >> 7;
    const int q0 = ds * 25;

    #pragma unroll 1
    for (int jc = 0; jc < 4; ++jc) {
        __syncthreads();                 // prior users of u_s / s_s done
        stage_u_async(u_s, u, bb, jc, tid);

        ull acc[4][4];
        #pragma unroll
        for (int i = 0; i < 4; ++i)
            #pragma unroll
            for (int k = 0; k < 4; ++k) acc[i][k] = 0ull;

        stage_wait();
        __syncthreads();                 // u chunk visible to all

        #pragma unroll 1
        for (int qi = 0; qi < 25; ++qi) {
            const int q = q0 + qi;
            f4u uu[4];
            #pragma unroll
            for (int k = 0; k < 4; ++k)
                uu[k].v = *reinterpret_cast<const float4*>(&u_s[(jt + 16 * k) * DP + 4 * q]);
            #pragma unroll
            for (int i = 0; i < 4; ++i) {
                f4u hw;
                hw.v = *reinterpret_cast<const float4*>(&hw_s[(rt * 4 + i) * DP + 4 * q]);
                #pragma unroll
                for (int k = 0; k < 4; ++k) {
                    ffma2(acc[i][k], hw.u[0], uu[k].u[0]);
                    ffma2(acc[i][k], hw.u[1], uu[k].u[1]);
                }
            }
        }

        // combine the two d halves through smem
        if (ds == 0) {
            #pragma unroll
            for (int i = 0; i < 4; ++i)
                #pragma unroll
                for (int k = 0; k < 4; ++k) {
                    f2u v; v.u = acc[i][k];
                    s_s[(rt * 4 + i) * JJ + jc * JC + jt + 16 * k] = v.f.x + v.f.y;
                }
        }
        __syncthreads();
        if (ds == 1) {
            #pragma unroll
            for (int i = 0; i < 4; ++i)
                #pragma unroll
                for (int k = 0; k < 4; ++k) {
                    f2u v; v.u = acc[i][k];
                    s_s[(rt * 4 + i) * JJ + jc * JC + jt + 16 * k] += v.f.x + v.f.y;
                }
        }
    }
    __syncthreads();

    // ---- softmax per row (adds alpha terms + bias) ----
    const float bias = __ldg(b_h) + __ldg(b_u) + __ldg(b_hu);
    #pragma unroll
    for (int k = 0; k < 4; ++k) {
        int r = wid * 4 + k;
        float ah = al_s[r] + bias;
        float vals[8];
        float mx = -3.4e38f;
        #pragma unroll
        for (int m = 0; m < 8; ++m) {
            vals[m] = s_s[r * JJ + lane + 32 * m] + ah + g_alpha_u[bb * JJ + lane + 32 * m];
            mx = fmaxf(mx, vals[m]);
        }
        #pragma unroll
        for (int o = 16; o > 0; o >>= 1) mx = fmaxf(mx, __shfl_xor_sync(0xffffffffu, mx, o));
        float sum = 0.f;
        #pragma unroll
        for (int m = 0; m < 8; ++m) {
            float e = __expf(vals[m] - mx);
            s_s[r * JJ + lane + 32 * m] = e;   // unnormalized exp
            sum += e;
        }
        #pragma unroll
        for (int o = 16; o > 0; o >>= 1) sum += __shfl_xor_sync(0xffffffffu, sum, o);
        if (lane == 0) {
            g_m[bb * TT + t0 + r] = mx;
            inv_s[r] = 1.0f / sum;
        }
    }

    // ---- PV: c2q[r][d] = inv[r] * sum_j a[r][j]*u[j][d] ----
    // thread: 2 rows, float4 d-groups dq = dqg + 8k (k<7, dq<50), j-subset by jg
    const int rg  = tid >> 4;         // rows 2rg, 2rg+1
    const int dqg = tid & 7;
    const int jg  = (tid >> 3) & 1;
    const int r0 = 2 * rg, r1 = r0 + 1;

    ull p0[7][2], p1[7][2];
    #pragma unroll
    for (int k = 0; k < 7; ++k) {
        p0[k][0] = p0[k][1] = 0ull;
        p1[k][0] = p1[k][1] = 0ull;
    }

    // reverse chunk order: chunk 3 is still resident from QK (skip its staging)
    #pragma unroll 1
    for (int jci = 0; jci < 4; ++jci) {
        const int jc = 3 - jci;
        if (jci > 0) {
            __syncthreads();
            stage_u_async(u_s, u, bb, jc, tid);
            stage_wait();
            __syncthreads();
        }
        #pragma unroll 2
        for (int jjl = 0; jjl < JC; jjl += 2) {
            int jl = jjl + jg;
            int j  = jc * JC + jl;
            ull a02 = bcast2(s_s[r0 * JJ + j]);
            ull a12 = bcast2(s_s[r1 * JJ + j]);
            #pragma unroll
            for (int k = 0; k < 7; ++k) {
                int dq = dqg + 8 * k;
                if (dq < 50) {
                    f4u u4;
                    u4.v = *reinterpret_cast<const float4*>(&u_s[jl * DP + 4 * dq]);
                    ffma2(p0[k][0], a02, u4.u[0]);
                    ffma2(p0[k][1], a02, u4.u[1]);
                    ffma2(p1[k][0], a12, u4.u[0]);
                    ffma2(p1[k][1], a12, u4.u[1]);
                }
            }
        }
    }
    __syncthreads();   // PV reads of u_s done before overlaying c2q_s

    // reduce over jg (shfl xor 8), scale, write c2q
    {
        float iv0 = inv_s[r0], iv1 = inv_s[r1];
        #pragma unroll
        for (int k = 0; k < 7; ++k) {
            int dq = dqg + 8 * k;
            float o0[4], o1[4];
            #pragma unroll
            for (int half = 0; half < 2; ++half) {
                f2u v0; v0.u = p0[k][half];
                f2u v1; v1.u = p1[k][half];
                v0.f.x += __shfl_xor_sync(0xffffffffu, v0.f.x, 8);
                v0.f.y += __shfl_xor_sync(0xffffffffu, v0.f.y, 8);
                v1.f.x += __shfl_xor_sync(0xffffffffu, v1.f.x, 8);
                v1.f.y += __shfl_xor_sync(0xffffffffu, v1.f.y, 8);
                o0[2 * half] = v0.f.x * iv0; o0[2 * half + 1] = v0.f.y * iv0;
                o1[2 * half] = v1.f.x * iv1; o1[2 * half + 1] = v1.f.y * iv1;
            }
            if (jg == 0 && dq < 50) {
                *reinterpret_cast<float4*>(&c2q_s[r0 * DP + 4 * dq]) = make_float4(o0[0], o0[1], o0[2], o0[3]);
                *reinterpret_cast<float4*>(&c2q_s[r1 * DP + 4 * dq]) = make_float4(o1[0], o1[1], o1[2], o1[3]);
            }
        }
    }
    __syncthreads();

    // ---- epilogue: g[:,D:2D]=c2q, g[:,2D:3D]=h*c2q (float4; h slot written by copy_h) ----
    float4* gbase = reinterpret_cast<float4*>(g + ((size_t)bb * TT + t0) * (4 * DD));
    #pragma unroll 4
    for (int i = tid; i < TROWS * 50; i += NTHREADS) {
        int r = i / 50, c = i % 50;
        float4 hv = hsrc4[i];
        float4 cq = *reinterpret_cast<const float4*>(&c2q_s[r * DP + 4 * c]);
        size_t ro = (size_t)r * 200;
        gbase[ro + 50 + c] = cq;
        float4 p; p.x = hv.x * cq.x; p.y = hv.y * cq.y; p.z = hv.z * cq.z; p.w = hv.w * cq.w;
        gbase[ro + 100 + c] = p;
    }
}

// ---------------------------------------------------------------------------
// beta[b,:] = softmax_t(m[b,:]) in place into g_m
// ---------------------------------------------------------------------------
__global__ __launch_bounds__(NTHREADS)
void beta_kernel() {
    __shared__ float red[8];
    const int b = blockIdx.x, tid = threadIdx.x;
    const int lane = tid & 31, wid = tid >> 5;

    float lm = -3.4e38f;
    float vals[8];
    #pragma unroll
    for (int k = 0; k < 8; ++k) {
        vals[k] = g_m[b * TT + tid + k * NTHREADS];
        lm = fmaxf(lm, vals[k]);
    }
    #pragma unroll
    for (int o = 16; o > 0; o >>= 1) lm = fmaxf(lm, __shfl_xor_sync(0xffffffffu, lm, o));
    if (lane == 0) red[wid] = lm;
    __syncthreads();
    float bm = red[0];
    #pragma unroll
    for (int i = 1; i < 8; ++i) bm = fmaxf(bm, red[i]);
    __syncthreads();

    float ls = 0.f;
    #pragma unroll
    for (int k = 0; k < 8; ++k) {
        vals[k] = __expf(vals[k] - bm);
        ls += vals[k];
    }
    #pragma unroll
    for (int o = 16; o > 0; o >>= 1) ls += __shfl_xor_sync(0xffffffffu, ls, o);
    if (lane == 0) red[wid] = ls;
    __syncthreads();
    float bs = 0.f;
    #pragma unroll
    for (int i = 0; i < 8; ++i) bs += red[i];
    const float inv = 1.0f / bs;
    #pragma unroll
    for (int k = 0; k < 8; ++k)
        g_m[b * TT + tid + k * NTHREADS] = vals[k] * inv;
}

// ---------------------------------------------------------------------------
__global__ __launch_bounds__(NTHREADS)
void q2c_part_kernel(const float* __restrict__ h) {
    const int p = blockIdx.x, b = blockIdx.y, tid = threadIdx.x;
    if (tid < DD) {
        const float* hb = h + ((size_t)b * TT + p * 256) * DD + tid;
        const float* bt = &g_m[b * TT + p * 256];
        float a0 = 0.f, a1 = 0.f, a2 = 0.f, a3 = 0.f;
        #pragma unroll 4
        for (int t = 0; t < 256; t += 4) {
            a0 += bt[t]     * hb[(size_t)t * DD];
            a1 += bt[t + 1] * hb[(size_t)(t + 1) * DD];
            a2 += bt[t + 2] * hb[(size_t)(t + 2) * DD];
            a3 += bt[t + 3] * hb[(size_t)(t + 3) * DD];
        }
        g_part[(b * 8 + p) * DD + tid] = a0 + a1 + a2 + a3;
    }
}

__global__ void q2c_reduce_kernel() {
    int idx = blockIdx.x * NTHREADS + threadIdx.x;
    if (idx < BB * DD) {
        int b = idx / DD, d = idx % DD;
        float s = 0.f;
        #pragma unroll
        for (int p = 0; p < 8; ++p) s += g_part[(b * 8 + p) * DD + d];
        g_q2c[idx] = s;
    }
}

// ---------------------------------------------------------------------------
__global__ void g3_kernel(const float* __restrict__ h, float* __restrict__ g) {
    int idx = blockIdx.x * NTHREADS + threadIdx.x;   // over B*T*50 float4
    int tl  = idx / 50;
    int c   = idx % 50;
    int b   = tl >> 11;
    float4 hv = reinterpret_cast<const float4*>(h)[idx];
    float4 q  = *reinterpret_cast<const float4*>(&g_q2c[b * DD + 4 * c]);
    float4 p; p.x = hv.x * q.x; p.y = hv.y * q.y; p.z = hv.z * q.z; p.w = hv.w * q.w;
    reinterpret_cast<float4*>(g)[(size_t)tl * 200 + 150 + c] = p;
}

// ---------------------------------------------------------------------------
extern "C" void kernel_launch(void* const* d_in, const int* in_sizes, int n_in,
                              void* d_out, int out_size) {
    const float* h    = (const float*)d_in[0];
    const float* u    = (const float*)d_in[1];
    const float* w_h  = (const float*)d_in[2];
    const float* b_h  = (const float*)d_in[3];
    const float* w_u  = (const float*)d_in[4];
    const float* b_u  = (const float*)d_in[5];
    const float* w_hu = (const float*)d_in[6];
    const float* b_hu = (const float*)d_in[7];
    float* g = (float*)d_out;

    const int smem_bytes = (TROWS * DP + JC * DP + TROWS * JJ + 2 * TROWS) * 4; // 111360
    cudaFuncSetAttribute(bidaf_main_kernel, cudaFuncAttributeMaxDynamicSharedMemorySize, smem_bytes);

    // launches 0-4 (so ncu -s 5 -c 1 captures bidaf_main)
    copy_h_kernel<<<(BB * TT * 50) / NTHREADS, NTHREADS>>>(h, g);
    for (int qtr = 0; qtr < 4; ++qtr)
        alpha_u_kernel<<<512, NTHREADS>>>(u, w_u, qtr * 4096);

    // launch 5: main (ncu target)
    dim3 gridC(TT / TROWS, BB);
    bidaf_main_kernel<<<gridC, NTHREADS, smem_bytes>>>(h, u, w_h, w_hu, b_h, b_u, b_hu, g);

    beta_kernel<<<BB, NTHREADS>>>();

    dim3 gridP(8, BB);
    q2c_part_kernel<<<gridP, NTHREADS>>>(h);
    q2c_reduce_kernel<<<(BB * DD + NTHREADS - 1) / NTHREADS, NTHREADS>>>();

    g3_kernel<<<(BB * TT * 50) / NTHREADS, NTHREADS>>>(h, g);
}